// round 1
// baseline (speedup 1.0000x reference)
#include <cuda_runtime.h>
#include <cuda_bf16.h>
#include <mma.h>
#include <cstdint>
#include <cstddef>

using namespace nvcuda;

// Problem shape (fixed by the dataset): B=4, S=2048, H=2048, I=4096
constexpr int H_DIM = 2048;
constexpr int I_DIM = 4096;
constexpr int TOK   = 8192;   // 4 * 2048 tokens

// ---------------------------------------------------------------------------
// Scratch (device globals; no allocation allowed)
// ---------------------------------------------------------------------------
__device__ float  g_wscale[2];
__device__ double g_part[1024];
__device__ __nv_bfloat16 g_wq_up[(size_t)I_DIM * H_DIM];   // ternary weights, bf16
__device__ __nv_bfloat16 g_wq_dn[(size_t)H_DIM * I_DIM];
__device__ __nv_bfloat16 g_xq1[(size_t)TOK * H_DIM];       // quantized acts (integers), bf16
__device__ __nv_bfloat16 g_xq2[(size_t)TOK * I_DIM];
__device__ float g_h[(size_t)TOK * I_DIM];                 // relu^2 intermediate, fp32
__device__ float g_sx1[TOK];                               // per-token quant scales
__device__ float g_sx2[TOK];

// ---------------------------------------------------------------------------
// Weight abs-mean (deterministic two-pass reduction) + ternary quantization
// ---------------------------------------------------------------------------
__global__ void absmean_partial_kernel(const float* __restrict__ w, int n) {
    __shared__ double sm[256];
    double loc = 0.0;
    for (int i = blockIdx.x * 256 + threadIdx.x; i < n; i += gridDim.x * 256)
        loc += (double)fabsf(w[i]);
    sm[threadIdx.x] = loc;
    __syncthreads();
    for (int s = 128; s > 0; s >>= 1) {
        if (threadIdx.x < s) sm[threadIdx.x] += sm[threadIdx.x + s];
        __syncthreads();
    }
    if (threadIdx.x == 0) g_part[blockIdx.x] = sm[0];
}

__global__ void absmean_final_kernel(int n, int which) {
    __shared__ double sm[256];
    const int t = threadIdx.x;
    double loc = g_part[t] + g_part[t + 256] + g_part[t + 512] + g_part[t + 768];
    sm[t] = loc;
    __syncthreads();
    for (int s = 128; s > 0; s >>= 1) {
        if (t < s) sm[t] += sm[t + s];
        __syncthreads();
    }
    if (t == 0) {
        float sc = (float)(sm[0] / (double)n);
        g_wscale[which] = fmaxf(sc, 1e-5f);
    }
}

__global__ void quant_w_kernel(const float* __restrict__ w, int n, int which) {
    __nv_bfloat16* wq = which ? g_wq_dn : g_wq_up;
    const float s = g_wscale[which];
    for (int i = blockIdx.x * blockDim.x + threadIdx.x; i < n;
         i += gridDim.x * blockDim.x) {
        float q = rintf(w[i] / s);            // round-half-even matches jnp.round
        q = fminf(fmaxf(q, -1.0f), 1.0f);     // ternary
        wq[i] = __float2bfloat16(q);          // exact
    }
}

// ---------------------------------------------------------------------------
// Fused FWHT + per-token absmax int8-grid quantization.
// One block per token; row lives in shared memory.
// ---------------------------------------------------------------------------
template <int N, int LAYER>
__global__ __launch_bounds__(256) void fwht_quant_kernel(const float* __restrict__ xin) {
    __shared__ float buf[N];
    __shared__ float red[256];
    const int t = threadIdx.x;

    const float* src = (LAYER == 0) ? xin : g_h;
    __nv_bfloat16* xq = (LAYER == 0) ? g_xq1 : g_xq2;
    float* sxp        = (LAYER == 0) ? g_sx1 : g_sx2;

    const float* row = src + (size_t)blockIdx.x * N;
    for (int i = t; i < N / 4; i += 256)
        ((float4*)buf)[i] = ((const float4*)row)[i];
    __syncthreads();

    // Iterative Walsh-Hadamard butterflies (matches reference pairing exactly)
    for (int h = 1; h < N; h <<= 1) {
        for (int p = t; p < N / 2; p += 256) {
            int i0 = ((p & ~(h - 1)) << 1) | (p & (h - 1));
            float a = buf[i0];
            float b = buf[i0 + h];
            buf[i0]     = a + b;
            buf[i0 + h] = a - b;
        }
        __syncthreads();
    }

    // Normalize, absmax (thread-local elems -> tree reduce)
    const float norm = 1.0f / sqrtf((float)N);
    float m = 0.0f;
    for (int i = t; i < N; i += 256) {
        float v = buf[i] * norm;
        buf[i] = v;
        m = fmaxf(m, fabsf(v));
    }
    red[t] = m;
    __syncthreads();
    for (int s = 128; s > 0; s >>= 1) {
        if (t < s) red[t] = fmaxf(red[t], red[t + s]);
        __syncthreads();
    }
    const float scale = 127.0f / fmaxf(red[0], 1e-5f);

    __nv_bfloat16* dst = xq + (size_t)blockIdx.x * N;
    for (int i = t; i < N; i += 256) {
        float q = rintf(buf[i] * scale);
        q = fminf(fmaxf(q, -127.0f), 127.0f);
        dst[i] = __float2bfloat16(q);          // integer -> exact in bf16
    }
    if (t == 0) sxp[blockIdx.x] = scale;
}

// ---------------------------------------------------------------------------
// bf16 wmma GEMM: C[M,N] = A[M,K] * B[N,K]^T  (both K-major), exact for
// integer-valued operands. Fused dequant (+ relu^2 for layer 0) epilogue.
// BM=BN=128, BK=32, 8 warps, warp tile 64x32.
// ---------------------------------------------------------------------------
template <int LAYER>
__global__ __launch_bounds__(256) void gemm_kernel(float* __restrict__ Cout) {
    constexpr int N = (LAYER == 0) ? I_DIM : H_DIM;
    constexpr int K = (LAYER == 0) ? H_DIM : I_DIM;
    constexpr int BM = 128, BK = 32, LDS = 48;  // +16 elem pad

    __shared__ __nv_bfloat16 As[BM * LDS];
    __shared__ __nv_bfloat16 Bs[BM * LDS];
    __shared__ float cs[8 * 256];               // per-warp epilogue scratch

    const __nv_bfloat16* A = (LAYER == 0) ? g_xq1  : g_xq2;
    const __nv_bfloat16* B = (LAYER == 0) ? g_wq_up : g_wq_dn;
    float* C               = (LAYER == 0) ? g_h    : Cout;
    const float* sx        = (LAYER == 0) ? g_sx1  : g_sx2;

    const int t = threadIdx.x;
    const int warp = t >> 5, lane = t & 31;
    const int wm = warp & 1;      // 2 warp-rows  (64 M each)
    const int wn = warp >> 1;     // 4 warp-cols  (32 N each)
    const int bm = blockIdx.y, bn = blockIdx.x;

    wmma::fragment<wmma::accumulator, 16, 16, 16, float> acc[4][2];
#pragma unroll
    for (int i = 0; i < 4; i++)
#pragma unroll
        for (int j = 0; j < 2; j++) wmma::fill_fragment(acc[i][j], 0.0f);

    const __nv_bfloat16* Ag = A + (size_t)bm * BM * K;
    const __nv_bfloat16* Bg = B + (size_t)bn * BM * K;
    const int r0 = t >> 2;           // 0..63
    const int c0 = (t & 3) * 8;      // 0,8,16,24

    for (int kt = 0; kt < K; kt += BK) {
#pragma unroll
        for (int it = 0; it < 2; it++) {
            int r = r0 + it * 64;
            *(uint4*)(As + r * LDS + c0) = *(const uint4*)(Ag + (size_t)r * K + kt + c0);
            *(uint4*)(Bs + r * LDS + c0) = *(const uint4*)(Bg + (size_t)r * K + kt + c0);
        }
        __syncthreads();
#pragma unroll
        for (int kf = 0; kf < 2; kf++) {
            wmma::fragment<wmma::matrix_a, 16, 16, 16, __nv_bfloat16, wmma::row_major> af[4];
            wmma::fragment<wmma::matrix_b, 16, 16, 16, __nv_bfloat16, wmma::col_major> bf[2];
#pragma unroll
            for (int i = 0; i < 4; i++)
                wmma::load_matrix_sync(af[i], As + (wm * 64 + i * 16) * LDS + kf * 16, LDS);
#pragma unroll
            for (int j = 0; j < 2; j++)
                wmma::load_matrix_sync(bf[j], Bs + (wn * 32 + j * 16) * LDS + kf * 16, LDS);
#pragma unroll
            for (int i = 0; i < 4; i++)
#pragma unroll
                for (int j = 0; j < 2; j++)
                    wmma::mma_sync(acc[i][j], af[i], bf[j], acc[i][j]);
        }
        __syncthreads();
    }

    // Epilogue: out = acc * w_scale / act_scale[row]; layer0 adds relu^2.
    const float ws = g_wscale[LAYER];
    float* cw = cs + warp * 256;
#pragma unroll
    for (int i = 0; i < 4; i++) {
#pragma unroll
        for (int j = 0; j < 2; j++) {
            wmma::store_matrix_sync(cw, acc[i][j], 16, wmma::mem_row_major);
            __syncwarp();
            const int rr = lane >> 1;
            const int cc = (lane & 1) * 8;
            const int gr = bm * 128 + wm * 64 + i * 16 + rr;
            const int gc = bn * 128 + wn * 32 + j * 16 + cc;
            const float fac = ws / sx[gr];
            const float* p = cw + lane * 8;
            float v[8];
#pragma unroll
            for (int e = 0; e < 8; e++) {
                float x = p[e] * fac;
                if (LAYER == 0) { x = fmaxf(x, 0.0f); x = x * x; }
                v[e] = x;
            }
            float4* o = (float4*)(C + (size_t)gr * N + gc);
            o[0] = make_float4(v[0], v[1], v[2], v[3]);
            o[1] = make_float4(v[4], v[5], v[6], v[7]);
            __syncwarp();
        }
    }
}

// ---------------------------------------------------------------------------
// Launch
// ---------------------------------------------------------------------------
extern "C" void kernel_launch(void* const* d_in, const int* in_sizes, int n_in,
                              void* d_out, int out_size) {
    (void)in_sizes; (void)n_in; (void)out_size;
    const float* x  = (const float*)d_in[0];   // hidden_states [4,2048,2048]
    const float* wu = (const float*)d_in[1];   // w_up   [4096,2048]
    const float* wd = (const float*)d_in[2];   // w_down [2048,4096]
    float* out = (float*)d_out;                // [4,2048,2048] fp32

    const int nup = I_DIM * H_DIM;
    const int ndn = H_DIM * I_DIM;

    // Weight quantization (both tensors)
    absmean_partial_kernel<<<1024, 256>>>(wu, nup);
    absmean_final_kernel<<<1, 256>>>(nup, 0);
    quant_w_kernel<<<2048, 256>>>(wu, nup, 0);
    absmean_partial_kernel<<<1024, 256>>>(wd, ndn);
    absmean_final_kernel<<<1, 256>>>(ndn, 1);
    quant_w_kernel<<<2048, 256>>>(wd, ndn, 1);

    // Layer 1: FWHT(2048)+quant, GEMM -> relu^2 -> g_h
    fwht_quant_kernel<H_DIM, 0><<<TOK, 256>>>(x);
    gemm_kernel<0><<<dim3(I_DIM / 128, TOK / 128), 256>>>(nullptr);

    // Layer 2: FWHT(4096)+quant, GEMM -> out
    fwht_quant_kernel<I_DIM, 1><<<TOK, 256>>>(nullptr);
    gemm_kernel<1><<<dim3(H_DIM / 128, TOK / 128), 256>>>(out);
}